// round 14
// baseline (speedup 1.0000x reference)
#include <cuda_runtime.h>
#include <cuda_fp16.h>
#include <math.h>
#include <stdint.h>

// ---------------------------------------------------------------------------
// MoE feed-forward, 1-term fp16 HMMA GEMMs (fp32 acc), rel_err ~4e-4.
// Round 13: pipeline restructure around the proven round-9 GEMM core:
//   - FFN1 routed + FFN1 shared fused into ONE launch (same shape, K=1024)
//   - g_Y eliminated: shared-FFN2 writes out first, routed-FFN2 atomicAdds
//     its weighted contribution (fp32) into out, skipping pad rows
//   - x->fp16 conversion folded into k_gate (cvt kernel converts weights only)
// ---------------------------------------------------------------------------

#define T_TOKENS 8192
#define DM 1024
#define DF 2048
#define N_EXP 8
#define MTILES 136
#define SLOTS (MTILES * 128)       // 17408
#define YS (T_TOKENS / 128)        // 64 shared-FFN1 tiles

#define BM 128
#define BN 128
#define BK 64
#define NTHREADS 256
#define LDSH 72                     // halves per smem row (144 bytes)
#define A_BYTES (128 * LDSH * 2)    // 18432
#define B_BYTES (128 * LDSH * 2)    // 18432
#define OFF_B A_BYTES
#define STG_BYTES (A_BYTES + B_BYTES)          // 36864
#define NSTAGE 3
#define DYN_SMEM (NSTAGE * STG_BYTES)          // 110592 (x2 CTAs = 221K/SM)

// ------------------------------- globals -----------------------------------
__device__ int   g_counts[N_EXP];
__device__ int   g_cursor[N_EXP];
__device__ int   g_poff[N_EXP + 1];
__device__ int   g_rout_e[T_TOKENS * 2];
__device__ float g_rout_w[T_TOKENS * 2];
__device__ int   g_seg_token[SLOTS];
__device__ float g_seg_w[SLOTS];

__device__ __half g_xh[(size_t)T_TOKENS * DM];
__device__ __half g_w1h[(size_t)N_EXP * DF * DM];
__device__ __half g_w2h[(size_t)N_EXP * DM * DF];
__device__ __half g_ws1h[(size_t)DF * DM];
__device__ __half g_ws2h[(size_t)DM * DF];
__device__ __half g_Hh[(size_t)SLOTS * DF];
__device__ __half g_Hsh[(size_t)T_TOKENS * DF];

// ------------------------------ asm helpers --------------------------------
__device__ __forceinline__ uint32_t smem_u32(const void* p) {
    return (uint32_t)__cvta_generic_to_shared(p);
}
__device__ __forceinline__ void cp16(uint32_t dst, const void* src) {
    asm volatile("cp.async.cg.shared.global [%0], [%1], 16;" :: "r"(dst), "l"(src));
}
#define CP_COMMIT() asm volatile("cp.async.commit_group;")
#define CP_WAIT(N)  asm volatile("cp.async.wait_group %0;" :: "n"(N))

__device__ __forceinline__ void ldm_x4(uint32_t& r0, uint32_t& r1, uint32_t& r2,
                                       uint32_t& r3, uint32_t addr) {
    asm volatile("ldmatrix.sync.aligned.m8n8.x4.shared.b16 {%0,%1,%2,%3}, [%4];"
                 : "=r"(r0), "=r"(r1), "=r"(r2), "=r"(r3) : "r"(addr));
}
__device__ __forceinline__ void mma16816(float& c0, float& c1, float& c2, float& c3,
                                         uint32_t a0, uint32_t a1, uint32_t a2,
                                         uint32_t a3, uint32_t b0, uint32_t b1) {
    asm volatile(
        "mma.sync.aligned.m16n8k16.row.col.f32.f16.f16.f32 "
        "{%0,%1,%2,%3}, {%4,%5,%6,%7}, {%8,%9}, {%0,%1,%2,%3};"
        : "+f"(c0), "+f"(c1), "+f"(c2), "+f"(c3)
        : "r"(a0), "r"(a1), "r"(a2), "r"(a3), "r"(b0), "r"(b1));
}

__device__ __forceinline__ unsigned pack2h(__half a, __half b) {
    return ((unsigned)__half_as_ushort(b) << 16) | (unsigned)__half_as_ushort(a);
}

// ------------------------------ routing kernels ----------------------------
__global__ void k_init() {
    int i = blockIdx.x * 256 + threadIdx.x;
    if (i < SLOTS) g_seg_token[i] = -1;
    if (i < N_EXP) { g_counts[i] = 0; g_cursor[i] = 0; }
}

// gate + x->fp16 conversion fused (gate already streams all of x)
__global__ __launch_bounds__(256) void k_gate(const float* __restrict__ x,
                                              const float* __restrict__ gw) {
    __shared__ __align__(16) float xs[DM];
    __shared__ float lg[N_EXP];
    int t = blockIdx.x;
    const float* xr = x + (size_t)t * DM;
    uint2* xh = reinterpret_cast<uint2*>(g_xh + (size_t)t * DM);
    for (int i = threadIdx.x; i < DM / 4; i += 256) {
        float4 v = reinterpret_cast<const float4*>(xr)[i];
        reinterpret_cast<float4*>(xs)[i] = v;
        uint2 H;
        H.x = pack2h(__float2half(v.x), __float2half(v.y));
        H.y = pack2h(__float2half(v.z), __float2half(v.w));
        xh[i] = H;
    }
    __syncthreads();
    int w = threadIdx.x >> 5, lane = threadIdx.x & 31;
    const float* ge = gw + w * DM;
    float s = 0.f;
    for (int d = lane; d < DM; d += 32) s += xs[d] * ge[d];
    for (int o = 16; o; o >>= 1) s += __shfl_xor_sync(0xffffffffu, s, o);
    if (lane == 0) lg[w] = s;
    __syncthreads();
    if (threadIdx.x == 0) {
        float mx = lg[0];
        #pragma unroll
        for (int e = 1; e < N_EXP; e++) mx = fmaxf(mx, lg[e]);
        float sm[N_EXP], den = 0.f;
        #pragma unroll
        for (int e = 0; e < N_EXP; e++) { sm[e] = expf(lg[e] - mx); den += sm[e]; }
        #pragma unroll
        for (int e = 0; e < N_EXP; e++) sm[e] /= den;
        int i0 = 0;
        #pragma unroll
        for (int e = 1; e < N_EXP; e++) if (sm[e] > sm[i0]) i0 = e;
        int i1 = -1;
        #pragma unroll
        for (int e = 0; e < N_EXP; e++) {
            if (e == i0) continue;
            if (i1 < 0 || sm[e] > sm[i1]) i1 = e;
        }
        float w0 = sm[i0], w1 = sm[i1];
        float dn = w0 + w1 + 1e-20f;
        w0 /= dn; w1 /= dn;
        g_rout_e[2 * t] = i0;  g_rout_e[2 * t + 1] = i1;
        g_rout_w[2 * t] = w0;  g_rout_w[2 * t + 1] = w1;
        atomicAdd(&g_counts[i0], 1);
        atomicAdd(&g_counts[i1], 1);
    }
}

__global__ void k_scan() {
    if (threadIdx.x == 0) {
        int off = 0;
        for (int e = 0; e < N_EXP; e++) {
            g_poff[e] = off;
            off += ((g_counts[e] + 127) >> 7) << 7;   // 128-aligned segments
        }
        g_poff[N_EXP] = off;
    }
}

__global__ void k_scatter() {
    int t = blockIdx.x * 256 + threadIdx.x;
    if (t >= T_TOKENS) return;
    #pragma unroll
    for (int k = 0; k < 2; k++) {
        int e = g_rout_e[2 * t + k];
        int pos = g_poff[e] + atomicAdd(&g_cursor[e], 1);
        g_seg_token[pos] = t;
        g_seg_w[pos] = g_rout_w[2 * t + k];
    }
}

// weight f32 -> fp16 conversion (x handled in k_gate)
#define NW1Q (N_EXP * DF * DM / 4)
#define NW2Q NW1Q
#define NS1Q (DF * DM / 4)
#define NS2Q NS1Q
#define NCVTW (NW1Q + NW2Q + NS1Q + NS2Q)

__global__ __launch_bounds__(256) void k_cvt_w(const float4* __restrict__ w1,
                                               const float4* __restrict__ w2,
                                               const float4* __restrict__ ws1,
                                               const float4* __restrict__ ws2) {
    long i = (long)blockIdx.x * 256 + threadIdx.x;
    if (i >= NCVTW) return;
    long o = i;
    const float4* src;
    uint2* dst;
    if (o < NW1Q)                { src = w1;  dst = (uint2*)g_w1h; }
    else if ((o -= NW1Q) < NW2Q) { src = w2;  dst = (uint2*)g_w2h; }
    else if ((o -= NW2Q) < NS1Q) { src = ws1; dst = (uint2*)g_ws1h; }
    else { o -= NS1Q;              src = ws2; dst = (uint2*)g_ws2h; }
    float4 f = src[o];
    uint2 H;
    H.x = pack2h(__float2half(f.x), __float2half(f.y));
    H.y = pack2h(__float2half(f.z), __float2half(f.w));
    dst[o] = H;
}

// ------------------------------ HMMA GEMM ----------------------------------
// modes: 0 = fused FFN1 (y<YS shared -> g_Hsh; else routed -> g_Hh)
//        3 = shared FFN2: out = Hs@ws2 + bs2 (plain store)
//        1 = routed FFN2: atomicAdd sw*(H@w2 + b2) into out, skip pads
__device__ __forceinline__ void stage_cp(uint32_t sb, const int* __restrict__ aoff,
                                         const __half* __restrict__ Ah,
                                         const __half* __restrict__ Bh,
                                         int kb, int K, int tid) {
    #pragma unroll
    for (int i = 0; i < 4; i++) {            // A: 128 rows x 8 16B-chunks
        int j = tid + i * NTHREADS;
        int r = j >> 3, q = j & 7;
        uint32_t d = sb + r * (LDSH * 2) + q * 16;
        size_t ga = (size_t)aoff[r] + kb + q * 8;
        cp16(d, Ah + ga);
    }
    #pragma unroll
    for (int i = 0; i < 4; i++) {            // B: 128 rows x 8 16B-chunks
        int j = tid + i * NTHREADS;
        int r = j >> 3, q = j & 7;
        uint32_t d = sb + OFF_B + r * (LDSH * 2) + q * 16;
        size_t gb = (size_t)r * K + kb + q * 8;
        cp16(d, Bh + gb);
    }
}

__global__ __launch_bounds__(NTHREADS, 2) void k_gemm(int mode, int K,
                                                      const float* __restrict__ bias0,
                                                      const float* __restrict__ bias1,
                                                      float* __restrict__ outp) {
    extern __shared__ __align__(16) char dsm[];
    __shared__ int s_aoff[BM];

    int tid = threadIdx.x;
    int lane = tid & 31, w = tid >> 5;       // 8 warps
    int wm = w & 1, wn = w >> 1;             // warp grid 2(M) x 4(N), tile 64x32
    int n0 = blockIdx.x * BN;

    bool shared_path = false;                // (mode 0 only)
    int m0;
    const __half *Ah, *Bh;
    const float* bias;
    if (mode == 0) {
        shared_path = (blockIdx.y < YS);
        if (shared_path) {
            m0 = blockIdx.y * BM;            // token rows
            Ah = g_xh;
            Bh = g_ws1h + (size_t)n0 * DM;
            bias = bias1 + n0;               // bs1
        } else {
            m0 = (blockIdx.y - YS) * BM;     // slot rows
            if (m0 >= g_poff[N_EXP]) return; // pad tile
            int e = N_EXP - 1;
            #pragma unroll
            for (int q = 0; q < N_EXP; q++)
                if (m0 < g_poff[q + 1]) { e = q; break; }
            Ah = g_xh;
            Bh = g_w1h + (size_t)(e * DF + n0) * DM;
            bias = bias0 + e * DF + n0;      // b1
        }
    } else if (mode == 1) {
        m0 = blockIdx.y * BM;                // slot rows
        if (m0 >= g_poff[N_EXP]) return;
        int e = N_EXP - 1;
        #pragma unroll
        for (int q = 0; q < N_EXP; q++)
            if (m0 < g_poff[q + 1]) { e = q; break; }
        Ah = g_Hh;
        Bh = g_w2h + (size_t)(e * DM + n0) * DF;
        bias = bias0 + e * DM + n0;          // b2
    } else {                                 // mode 3
        m0 = blockIdx.y * BM;                // token rows
        Ah = g_Hsh;
        Bh = g_ws2h + (size_t)n0 * DF;
        bias = bias0 + n0;                   // bs2
    }

    if (tid < BM) {
        int r = m0 + tid;
        int off;
        if (mode == 0) {
            if (shared_path) off = r * DM;
            else { int tok = g_seg_token[r]; if (tok < 0) tok = 0; off = tok * DM; }
        } else off = r * DF;
        s_aoff[tid] = off;
    }
    __syncthreads();

    uint32_t sb0 = smem_u32(dsm);
    float acc[4][4][4];
    #pragma unroll
    for (int mt = 0; mt < 4; mt++)
        #pragma unroll
        for (int nt = 0; nt < 4; nt++)
            #pragma unroll
            for (int v = 0; v < 4; v++) acc[mt][nt][v] = 0.f;

    uint32_t a_row = wm * 64 + (lane & 15);
    uint32_t a_kof = (lane >> 4) * 8;
    uint32_t b_row = wn * 32 + (lane & 7) + ((lane >> 4) << 3);
    uint32_t b_kof = ((lane >> 3) & 1) * 8;

    const int NC = K / BK;
    stage_cp(sb0 + 0 * STG_BYTES, s_aoff, Ah, Bh, 0 * BK, K, tid);
    CP_COMMIT();
    stage_cp(sb0 + 1 * STG_BYTES, s_aoff, Ah, Bh, 1 * BK, K, tid);
    CP_COMMIT();

    int st = 0;
    for (int c = 0; c < NC; c++) {
        if (c + 1 < NC) { CP_WAIT(1); } else { CP_WAIT(0); }
        __syncthreads();
        if (c + 2 < NC) {
            int st2 = st + 2; if (st2 >= NSTAGE) st2 -= NSTAGE;
            stage_cp(sb0 + st2 * STG_BYTES, s_aoff, Ah, Bh, (c + 2) * BK, K, tid);
            CP_COMMIT();
        }

        uint32_t sbu = sb0 + st * STG_BYTES;
        #pragma unroll
        for (int ks = 0; ks < 4; ks++) {
            int kh = ks * 16;
            uint32_t bh[8];
            #pragma unroll
            for (int p = 0; p < 2; p++) {
                uint32_t ba = sbu + OFF_B +
                              ((b_row + p * 16) * LDSH + kh + b_kof) * 2;
                ldm_x4(bh[4 * p], bh[4 * p + 1], bh[4 * p + 2], bh[4 * p + 3], ba);
            }
            #pragma unroll
            for (int mt = 0; mt < 4; mt++) {
                uint32_t ah[4];
                uint32_t aa = sbu + ((a_row + mt * 16) * LDSH + kh + a_kof) * 2;
                ldm_x4(ah[0], ah[1], ah[2], ah[3], aa);
                #pragma unroll
                for (int nt = 0; nt < 4; nt++) {
                    uint32_t b0 = bh[(nt >> 1) * 4 + (nt & 1) * 2];
                    uint32_t b1 = bh[(nt >> 1) * 4 + (nt & 1) * 2 + 1];
                    float* A4 = acc[mt][nt];
                    mma16816(A4[0], A4[1], A4[2], A4[3],
                             ah[0], ah[1], ah[2], ah[3], b0, b1);
                }
            }
        }
        st++; if (st >= NSTAGE) st = 0;
    }
    __syncthreads();

    // ---------------- epilogue ----------------
    int g = lane >> 2, tig = lane & 3;
    #pragma unroll
    for (int mt = 0; mt < 4; mt++) {
        int row0 = m0 + wm * 64 + mt * 16 + g;
        int row8 = row0 + 8;
        float sw0 = 0.f, sw8 = 0.f;
        int t0 = 0, t8 = 0;
        if (mode == 1) {
            t0 = g_seg_token[row0]; t8 = g_seg_token[row8];
            sw0 = g_seg_w[row0];    sw8 = g_seg_w[row8];
        }
        #pragma unroll
        for (int nt = 0; nt < 4; nt++) {
            int colt = wn * 32 + nt * 8 + tig * 2;
            int ncol = n0 + colt;
            float b0v = bias[colt], b1v = bias[colt + 1];
            float c0 = acc[mt][nt][0], c1 = acc[mt][nt][1];
            float c2 = acc[mt][nt][2], c3 = acc[mt][nt][3];
            if (mode == 0) {
                __half* Hh = shared_path ? g_Hsh : g_Hh;
                float v00 = fmaxf(c0 + b0v, 0.f), v01 = fmaxf(c1 + b1v, 0.f);
                float v10 = fmaxf(c2 + b0v, 0.f), v11 = fmaxf(c3 + b1v, 0.f);
                *reinterpret_cast<unsigned*>(Hh + (size_t)row0 * DF + ncol) =
                    pack2h(__float2half(v00), __float2half(v01));
                *reinterpret_cast<unsigned*>(Hh + (size_t)row8 * DF + ncol) =
                    pack2h(__float2half(v10), __float2half(v11));
            } else if (mode == 3) {
                float2 o0 = make_float2(c0 + b0v, c1 + b1v);
                float2 o1 = make_float2(c2 + b0v, c3 + b1v);
                *reinterpret_cast<float2*>(outp + (size_t)row0 * DM + ncol) = o0;
                *reinterpret_cast<float2*>(outp + (size_t)row8 * DM + ncol) = o1;
            } else {
                if (t0 >= 0) {
                    atomicAdd(outp + (size_t)t0 * DM + ncol,     (c0 + b0v) * sw0);
                    atomicAdd(outp + (size_t)t0 * DM + ncol + 1, (c1 + b1v) * sw0);
                }
                if (t8 >= 0) {
                    atomicAdd(outp + (size_t)t8 * DM + ncol,     (c2 + b0v) * sw8);
                    atomicAdd(outp + (size_t)t8 * DM + ncol + 1, (c3 + b1v) * sw8);
                }
            }
        }
    }
}

// ------------------------------ host launch --------------------------------
extern "C" void kernel_launch(void* const* d_in, const int* in_sizes, int n_in,
                              void* d_out, int out_size) {
    const float* x   = (const float*)d_in[0];
    const float* gw  = (const float*)d_in[1];
    const float* w1  = (const float*)d_in[2];
    const float* b1  = (const float*)d_in[3];
    const float* w2  = (const float*)d_in[4];
    const float* b2  = (const float*)d_in[5];
    const float* ws1 = (const float*)d_in[6];
    const float* bs1 = (const float*)d_in[7];
    const float* ws2 = (const float*)d_in[8];
    const float* bs2 = (const float*)d_in[9];
    float* out = (float*)d_out;

    static bool attr_set = false;
    if (!attr_set) {
        cudaFuncSetAttribute(k_gemm, cudaFuncAttributeMaxDynamicSharedMemorySize,
                             DYN_SMEM);
        attr_set = true;
    }

    k_init<<<(SLOTS + 255) / 256, 256>>>();
    k_gate<<<T_TOKENS, 256>>>(x, gw);
    k_scan<<<1, 32>>>();
    k_scatter<<<T_TOKENS / 256, 256>>>();
    k_cvt_w<<<(NCVTW + 255) / 256, 256>>>((const float4*)w1, (const float4*)w2,
                                          (const float4*)ws1, (const float4*)ws2);
    // fused FFN1 (shared tiles y<YS, routed tiles after)
    k_gemm<<<dim3(DF / BN, YS + MTILES), NTHREADS, DYN_SMEM>>>(0, DM, b1, bs1, nullptr);
    // shared FFN2 -> writes out
    k_gemm<<<dim3(DM / BN, T_TOKENS / BM), NTHREADS, DYN_SMEM>>>(3, DF, bs2, nullptr, out);
    // routed FFN2 -> atomic accumulate into out
    k_gemm<<<dim3(DM / BN, MTILES), NTHREADS, DYN_SMEM>>>(1, DF, b2, nullptr, out);
}

// round 15
// speedup vs baseline: 1.0006x; 1.0006x over previous
#include <cuda_runtime.h>
#include <cuda_fp16.h>
#include <math.h>
#include <stdint.h>

// ---------------------------------------------------------------------------
// MoE feed-forward, 1-term fp16 HMMA GEMMs (fp32 acc), rel_err ~4e-4.
// Round 13: pipeline restructure around the proven round-9 GEMM core:
//   - FFN1 routed + FFN1 shared fused into ONE launch (same shape, K=1024)
//   - g_Y eliminated: shared-FFN2 writes out first, routed-FFN2 atomicAdds
//     its weighted contribution (fp32) into out, skipping pad rows
//   - x->fp16 conversion folded into k_gate (cvt kernel converts weights only)
// ---------------------------------------------------------------------------

#define T_TOKENS 8192
#define DM 1024
#define DF 2048
#define N_EXP 8
#define MTILES 136
#define SLOTS (MTILES * 128)       // 17408
#define YS (T_TOKENS / 128)        // 64 shared-FFN1 tiles

#define BM 128
#define BN 128
#define BK 64
#define NTHREADS 256
#define LDSH 72                     // halves per smem row (144 bytes)
#define A_BYTES (128 * LDSH * 2)    // 18432
#define B_BYTES (128 * LDSH * 2)    // 18432
#define OFF_B A_BYTES
#define STG_BYTES (A_BYTES + B_BYTES)          // 36864
#define NSTAGE 3
#define DYN_SMEM (NSTAGE * STG_BYTES)          // 110592 (x2 CTAs = 221K/SM)

// ------------------------------- globals -----------------------------------
__device__ int   g_counts[N_EXP];
__device__ int   g_cursor[N_EXP];
__device__ int   g_poff[N_EXP + 1];
__device__ int   g_rout_e[T_TOKENS * 2];
__device__ float g_rout_w[T_TOKENS * 2];
__device__ int   g_seg_token[SLOTS];
__device__ float g_seg_w[SLOTS];

__device__ __half g_xh[(size_t)T_TOKENS * DM];
__device__ __half g_w1h[(size_t)N_EXP * DF * DM];
__device__ __half g_w2h[(size_t)N_EXP * DM * DF];
__device__ __half g_ws1h[(size_t)DF * DM];
__device__ __half g_ws2h[(size_t)DM * DF];
__device__ __half g_Hh[(size_t)SLOTS * DF];
__device__ __half g_Hsh[(size_t)T_TOKENS * DF];

// ------------------------------ asm helpers --------------------------------
__device__ __forceinline__ uint32_t smem_u32(const void* p) {
    return (uint32_t)__cvta_generic_to_shared(p);
}
__device__ __forceinline__ void cp16(uint32_t dst, const void* src) {
    asm volatile("cp.async.cg.shared.global [%0], [%1], 16;" :: "r"(dst), "l"(src));
}
#define CP_COMMIT() asm volatile("cp.async.commit_group;")
#define CP_WAIT(N)  asm volatile("cp.async.wait_group %0;" :: "n"(N))

__device__ __forceinline__ void ldm_x4(uint32_t& r0, uint32_t& r1, uint32_t& r2,
                                       uint32_t& r3, uint32_t addr) {
    asm volatile("ldmatrix.sync.aligned.m8n8.x4.shared.b16 {%0,%1,%2,%3}, [%4];"
                 : "=r"(r0), "=r"(r1), "=r"(r2), "=r"(r3) : "r"(addr));
}
__device__ __forceinline__ void mma16816(float& c0, float& c1, float& c2, float& c3,
                                         uint32_t a0, uint32_t a1, uint32_t a2,
                                         uint32_t a3, uint32_t b0, uint32_t b1) {
    asm volatile(
        "mma.sync.aligned.m16n8k16.row.col.f32.f16.f16.f32 "
        "{%0,%1,%2,%3}, {%4,%5,%6,%7}, {%8,%9}, {%0,%1,%2,%3};"
        : "+f"(c0), "+f"(c1), "+f"(c2), "+f"(c3)
        : "r"(a0), "r"(a1), "r"(a2), "r"(a3), "r"(b0), "r"(b1));
}

__device__ __forceinline__ unsigned pack2h(__half a, __half b) {
    return ((unsigned)__half_as_ushort(b) << 16) | (unsigned)__half_as_ushort(a);
}

// ------------------------------ routing kernels ----------------------------
__global__ void k_init() {
    int i = blockIdx.x * 256 + threadIdx.x;
    if (i < SLOTS) g_seg_token[i] = -1;
    if (i < N_EXP) { g_counts[i] = 0; g_cursor[i] = 0; }
}

// gate + x->fp16 conversion fused (gate already streams all of x)
__global__ __launch_bounds__(256) void k_gate(const float* __restrict__ x,
                                              const float* __restrict__ gw) {
    __shared__ __align__(16) float xs[DM];
    __shared__ float lg[N_EXP];
    int t = blockIdx.x;
    const float* xr = x + (size_t)t * DM;
    uint2* xh = reinterpret_cast<uint2*>(g_xh + (size_t)t * DM);
    for (int i = threadIdx.x; i < DM / 4; i += 256) {
        float4 v = reinterpret_cast<const float4*>(xr)[i];
        reinterpret_cast<float4*>(xs)[i] = v;
        uint2 H;
        H.x = pack2h(__float2half(v.x), __float2half(v.y));
        H.y = pack2h(__float2half(v.z), __float2half(v.w));
        xh[i] = H;
    }
    __syncthreads();
    int w = threadIdx.x >> 5, lane = threadIdx.x & 31;
    const float* ge = gw + w * DM;
    float s = 0.f;
    for (int d = lane; d < DM; d += 32) s += xs[d] * ge[d];
    for (int o = 16; o; o >>= 1) s += __shfl_xor_sync(0xffffffffu, s, o);
    if (lane == 0) lg[w] = s;
    __syncthreads();
    if (threadIdx.x == 0) {
        float mx = lg[0];
        #pragma unroll
        for (int e = 1; e < N_EXP; e++) mx = fmaxf(mx, lg[e]);
        float sm[N_EXP], den = 0.f;
        #pragma unroll
        for (int e = 0; e < N_EXP; e++) { sm[e] = expf(lg[e] - mx); den += sm[e]; }
        #pragma unroll
        for (int e = 0; e < N_EXP; e++) sm[e] /= den;
        int i0 = 0;
        #pragma unroll
        for (int e = 1; e < N_EXP; e++) if (sm[e] > sm[i0]) i0 = e;
        int i1 = -1;
        #pragma unroll
        for (int e = 0; e < N_EXP; e++) {
            if (e == i0) continue;
            if (i1 < 0 || sm[e] > sm[i1]) i1 = e;
        }
        float w0 = sm[i0], w1 = sm[i1];
        float dn = w0 + w1 + 1e-20f;
        w0 /= dn; w1 /= dn;
        g_rout_e[2 * t] = i0;  g_rout_e[2 * t + 1] = i1;
        g_rout_w[2 * t] = w0;  g_rout_w[2 * t + 1] = w1;
        atomicAdd(&g_counts[i0], 1);
        atomicAdd(&g_counts[i1], 1);
    }
}

__global__ void k_scan() {
    if (threadIdx.x == 0) {
        int off = 0;
        for (int e = 0; e < N_EXP; e++) {
            g_poff[e] = off;
            off += ((g_counts[e] + 127) >> 7) << 7;   // 128-aligned segments
        }
        g_poff[N_EXP] = off;
    }
}

__global__ void k_scatter() {
    int t = blockIdx.x * 256 + threadIdx.x;
    if (t >= T_TOKENS) return;
    #pragma unroll
    for (int k = 0; k < 2; k++) {
        int e = g_rout_e[2 * t + k];
        int pos = g_poff[e] + atomicAdd(&g_cursor[e], 1);
        g_seg_token[pos] = t;
        g_seg_w[pos] = g_rout_w[2 * t + k];
    }
}

// weight f32 -> fp16 conversion (x handled in k_gate)
#define NW1Q (N_EXP * DF * DM / 4)
#define NW2Q NW1Q
#define NS1Q (DF * DM / 4)
#define NS2Q NS1Q
#define NCVTW (NW1Q + NW2Q + NS1Q + NS2Q)

__global__ __launch_bounds__(256) void k_cvt_w(const float4* __restrict__ w1,
                                               const float4* __restrict__ w2,
                                               const float4* __restrict__ ws1,
                                               const float4* __restrict__ ws2) {
    long i = (long)blockIdx.x * 256 + threadIdx.x;
    if (i >= NCVTW) return;
    long o = i;
    const float4* src;
    uint2* dst;
    if (o < NW1Q)                { src = w1;  dst = (uint2*)g_w1h; }
    else if ((o -= NW1Q) < NW2Q) { src = w2;  dst = (uint2*)g_w2h; }
    else if ((o -= NW2Q) < NS1Q) { src = ws1; dst = (uint2*)g_ws1h; }
    else { o -= NS1Q;              src = ws2; dst = (uint2*)g_ws2h; }
    float4 f = src[o];
    uint2 H;
    H.x = pack2h(__float2half(f.x), __float2half(f.y));
    H.y = pack2h(__float2half(f.z), __float2half(f.w));
    dst[o] = H;
}

// ------------------------------ HMMA GEMM ----------------------------------
// modes: 0 = fused FFN1 (y<YS shared -> g_Hsh; else routed -> g_Hh)
//        3 = shared FFN2: out = Hs@ws2 + bs2 (plain store)
//        1 = routed FFN2: atomicAdd sw*(H@w2 + b2) into out, skip pads
__device__ __forceinline__ void stage_cp(uint32_t sb, const int* __restrict__ aoff,
                                         const __half* __restrict__ Ah,
                                         const __half* __restrict__ Bh,
                                         int kb, int K, int tid) {
    #pragma unroll
    for (int i = 0; i < 4; i++) {            // A: 128 rows x 8 16B-chunks
        int j = tid + i * NTHREADS;
        int r = j >> 3, q = j & 7;
        uint32_t d = sb + r * (LDSH * 2) + q * 16;
        size_t ga = (size_t)aoff[r] + kb + q * 8;
        cp16(d, Ah + ga);
    }
    #pragma unroll
    for (int i = 0; i < 4; i++) {            // B: 128 rows x 8 16B-chunks
        int j = tid + i * NTHREADS;
        int r = j >> 3, q = j & 7;
        uint32_t d = sb + OFF_B + r * (LDSH * 2) + q * 16;
        size_t gb = (size_t)r * K + kb + q * 8;
        cp16(d, Bh + gb);
    }
}

__global__ __launch_bounds__(NTHREADS, 2) void k_gemm(int mode, int K,
                                                      const float* __restrict__ bias0,
                                                      const float* __restrict__ bias1,
                                                      float* __restrict__ outp) {
    extern __shared__ __align__(16) char dsm[];
    __shared__ int s_aoff[BM];

    int tid = threadIdx.x;
    int lane = tid & 31, w = tid >> 5;       // 8 warps
    int wm = w & 1, wn = w >> 1;             // warp grid 2(M) x 4(N), tile 64x32
    int n0 = blockIdx.x * BN;

    bool shared_path = false;                // (mode 0 only)
    int m0;
    const __half *Ah, *Bh;
    const float* bias;
    if (mode == 0) {
        shared_path = (blockIdx.y < YS);
        if (shared_path) {
            m0 = blockIdx.y * BM;            // token rows
            Ah = g_xh;
            Bh = g_ws1h + (size_t)n0 * DM;
            bias = bias1 + n0;               // bs1
        } else {
            m0 = (blockIdx.y - YS) * BM;     // slot rows
            if (m0 >= g_poff[N_EXP]) return; // pad tile
            int e = N_EXP - 1;
            #pragma unroll
            for (int q = 0; q < N_EXP; q++)
                if (m0 < g_poff[q + 1]) { e = q; break; }
            Ah = g_xh;
            Bh = g_w1h + (size_t)(e * DF + n0) * DM;
            bias = bias0 + e * DF + n0;      // b1
        }
    } else if (mode == 1) {
        m0 = blockIdx.y * BM;                // slot rows
        if (m0 >= g_poff[N_EXP]) return;
        int e = N_EXP - 1;
        #pragma unroll
        for (int q = 0; q < N_EXP; q++)
            if (m0 < g_poff[q + 1]) { e = q; break; }
        Ah = g_Hh;
        Bh = g_w2h + (size_t)(e * DM + n0) * DF;
        bias = bias0 + e * DM + n0;          // b2
    } else {                                 // mode 3
        m0 = blockIdx.y * BM;                // token rows
        Ah = g_Hsh;
        Bh = g_ws2h + (size_t)n0 * DF;
        bias = bias0 + n0;                   // bs2
    }

    if (tid < BM) {
        int r = m0 + tid;
        int off;
        if (mode == 0) {
            if (shared_path) off = r * DM;
            else { int tok = g_seg_token[r]; if (tok < 0) tok = 0; off = tok * DM; }
        } else off = r * DF;
        s_aoff[tid] = off;
    }
    __syncthreads();

    uint32_t sb0 = smem_u32(dsm);
    float acc[4][4][4];
    #pragma unroll
    for (int mt = 0; mt < 4; mt++)
        #pragma unroll
        for (int nt = 0; nt < 4; nt++)
            #pragma unroll
            for (int v = 0; v < 4; v++) acc[mt][nt][v] = 0.f;

    uint32_t a_row = wm * 64 + (lane & 15);
    uint32_t a_kof = (lane >> 4) * 8;
    uint32_t b_row = wn * 32 + (lane & 7) + ((lane >> 4) << 3);
    uint32_t b_kof = ((lane >> 3) & 1) * 8;

    const int NC = K / BK;
    stage_cp(sb0 + 0 * STG_BYTES, s_aoff, Ah, Bh, 0 * BK, K, tid);
    CP_COMMIT();
    stage_cp(sb0 + 1 * STG_BYTES, s_aoff, Ah, Bh, 1 * BK, K, tid);
    CP_COMMIT();

    int st = 0;
    for (int c = 0; c < NC; c++) {
        if (c + 1 < NC) { CP_WAIT(1); } else { CP_WAIT(0); }
        __syncthreads();
        if (c + 2 < NC) {
            int st2 = st + 2; if (st2 >= NSTAGE) st2 -= NSTAGE;
            stage_cp(sb0 + st2 * STG_BYTES, s_aoff, Ah, Bh, (c + 2) * BK, K, tid);
            CP_COMMIT();
        }

        uint32_t sbu = sb0 + st * STG_BYTES;
        #pragma unroll
        for (int ks = 0; ks < 4; ks++) {
            int kh = ks * 16;
            uint32_t bh[8];
            #pragma unroll
            for (int p = 0; p < 2; p++) {
                uint32_t ba = sbu + OFF_B +
                              ((b_row + p * 16) * LDSH + kh + b_kof) * 2;
                ldm_x4(bh[4 * p], bh[4 * p + 1], bh[4 * p + 2], bh[4 * p + 3], ba);
            }
            #pragma unroll
            for (int mt = 0; mt < 4; mt++) {
                uint32_t ah[4];
                uint32_t aa = sbu + ((a_row + mt * 16) * LDSH + kh + a_kof) * 2;
                ldm_x4(ah[0], ah[1], ah[2], ah[3], aa);
                #pragma unroll
                for (int nt = 0; nt < 4; nt++) {
                    uint32_t b0 = bh[(nt >> 1) * 4 + (nt & 1) * 2];
                    uint32_t b1 = bh[(nt >> 1) * 4 + (nt & 1) * 2 + 1];
                    float* A4 = acc[mt][nt];
                    mma16816(A4[0], A4[1], A4[2], A4[3],
                             ah[0], ah[1], ah[2], ah[3], b0, b1);
                }
            }
        }
        st++; if (st >= NSTAGE) st = 0;
    }
    __syncthreads();

    // ---------------- epilogue ----------------
    int g = lane >> 2, tig = lane & 3;
    #pragma unroll
    for (int mt = 0; mt < 4; mt++) {
        int row0 = m0 + wm * 64 + mt * 16 + g;
        int row8 = row0 + 8;
        float sw0 = 0.f, sw8 = 0.f;
        int t0 = 0, t8 = 0;
        if (mode == 1) {
            t0 = g_seg_token[row0]; t8 = g_seg_token[row8];
            sw0 = g_seg_w[row0];    sw8 = g_seg_w[row8];
        }
        #pragma unroll
        for (int nt = 0; nt < 4; nt++) {
            int colt = wn * 32 + nt * 8 + tig * 2;
            int ncol = n0 + colt;
            float b0v = bias[colt], b1v = bias[colt + 1];
            float c0 = acc[mt][nt][0], c1 = acc[mt][nt][1];
            float c2 = acc[mt][nt][2], c3 = acc[mt][nt][3];
            if (mode == 0) {
                __half* Hh = shared_path ? g_Hsh : g_Hh;
                float v00 = fmaxf(c0 + b0v, 0.f), v01 = fmaxf(c1 + b1v, 0.f);
                float v10 = fmaxf(c2 + b0v, 0.f), v11 = fmaxf(c3 + b1v, 0.f);
                *reinterpret_cast<unsigned*>(Hh + (size_t)row0 * DF + ncol) =
                    pack2h(__float2half(v00), __float2half(v01));
                *reinterpret_cast<unsigned*>(Hh + (size_t)row8 * DF + ncol) =
                    pack2h(__float2half(v10), __float2half(v11));
            } else if (mode == 3) {
                float2 o0 = make_float2(c0 + b0v, c1 + b1v);
                float2 o1 = make_float2(c2 + b0v, c3 + b1v);
                *reinterpret_cast<float2*>(outp + (size_t)row0 * DM + ncol) = o0;
                *reinterpret_cast<float2*>(outp + (size_t)row8 * DM + ncol) = o1;
            } else {
                if (t0 >= 0) {
                    atomicAdd(outp + (size_t)t0 * DM + ncol,     (c0 + b0v) * sw0);
                    atomicAdd(outp + (size_t)t0 * DM + ncol + 1, (c1 + b1v) * sw0);
                }
                if (t8 >= 0) {
                    atomicAdd(outp + (size_t)t8 * DM + ncol,     (c2 + b0v) * sw8);
                    atomicAdd(outp + (size_t)t8 * DM + ncol + 1, (c3 + b1v) * sw8);
                }
            }
        }
    }
}

// ------------------------------ host launch --------------------------------
extern "C" void kernel_launch(void* const* d_in, const int* in_sizes, int n_in,
                              void* d_out, int out_size) {
    const float* x   = (const float*)d_in[0];
    const float* gw  = (const float*)d_in[1];
    const float* w1  = (const float*)d_in[2];
    const float* b1  = (const float*)d_in[3];
    const float* w2  = (const float*)d_in[4];
    const float* b2  = (const float*)d_in[5];
    const float* ws1 = (const float*)d_in[6];
    const float* bs1 = (const float*)d_in[7];
    const float* ws2 = (const float*)d_in[8];
    const float* bs2 = (const float*)d_in[9];
    float* out = (float*)d_out;

    static bool attr_set = false;
    if (!attr_set) {
        cudaFuncSetAttribute(k_gemm, cudaFuncAttributeMaxDynamicSharedMemorySize,
                             DYN_SMEM);
        attr_set = true;
    }

    k_init<<<(SLOTS + 255) / 256, 256>>>();
    k_gate<<<T_TOKENS, 256>>>(x, gw);
    k_scan<<<1, 32>>>();
    k_scatter<<<T_TOKENS / 256, 256>>>();
    k_cvt_w<<<(NCVTW + 255) / 256, 256>>>((const float4*)w1, (const float4*)w2,
                                          (const float4*)ws1, (const float4*)ws2);
    // fused FFN1 (shared tiles y<YS, routed tiles after)
    k_gemm<<<dim3(DF / BN, YS + MTILES), NTHREADS, DYN_SMEM>>>(0, DM, b1, bs1, nullptr);
    // shared FFN2 -> writes out
    k_gemm<<<dim3(DM / BN, T_TOKENS / BM), NTHREADS, DYN_SMEM>>>(3, DF, bs2, nullptr, out);
    // routed FFN2 -> atomic accumulate into out
    k_gemm<<<dim3(DM / BN, MTILES), NTHREADS, DYN_SMEM>>>(1, DF, b2, nullptr, out);
}

// round 16
// speedup vs baseline: 1.0033x; 1.0027x over previous
#include <cuda_runtime.h>
#include <cuda_fp16.h>
#include <math.h>
#include <stdint.h>

// ---------------------------------------------------------------------------
// MoE feed-forward, 1-term fp16 HMMA GEMMs (fp32 acc), rel_err ~4e-4.
// Round 13: pipeline restructure around the proven round-9 GEMM core:
//   - FFN1 routed + FFN1 shared fused into ONE launch (same shape, K=1024)
//   - g_Y eliminated: shared-FFN2 writes out first, routed-FFN2 atomicAdds
//     its weighted contribution (fp32) into out, skipping pad rows
//   - x->fp16 conversion folded into k_gate (cvt kernel converts weights only)
// ---------------------------------------------------------------------------

#define T_TOKENS 8192
#define DM 1024
#define DF 2048
#define N_EXP 8
#define MTILES 136
#define SLOTS (MTILES * 128)       // 17408
#define YS (T_TOKENS / 128)        // 64 shared-FFN1 tiles

#define BM 128
#define BN 128
#define BK 64
#define NTHREADS 256
#define LDSH 72                     // halves per smem row (144 bytes)
#define A_BYTES (128 * LDSH * 2)    // 18432
#define B_BYTES (128 * LDSH * 2)    // 18432
#define OFF_B A_BYTES
#define STG_BYTES (A_BYTES + B_BYTES)          // 36864
#define NSTAGE 3
#define DYN_SMEM (NSTAGE * STG_BYTES)          // 110592 (x2 CTAs = 221K/SM)

// ------------------------------- globals -----------------------------------
__device__ int   g_counts[N_EXP];
__device__ int   g_cursor[N_EXP];
__device__ int   g_poff[N_EXP + 1];
__device__ int   g_rout_e[T_TOKENS * 2];
__device__ float g_rout_w[T_TOKENS * 2];
__device__ int   g_seg_token[SLOTS];
__device__ float g_seg_w[SLOTS];

__device__ __half g_xh[(size_t)T_TOKENS * DM];
__device__ __half g_w1h[(size_t)N_EXP * DF * DM];
__device__ __half g_w2h[(size_t)N_EXP * DM * DF];
__device__ __half g_ws1h[(size_t)DF * DM];
__device__ __half g_ws2h[(size_t)DM * DF];
__device__ __half g_Hh[(size_t)SLOTS * DF];
__device__ __half g_Hsh[(size_t)T_TOKENS * DF];

// ------------------------------ asm helpers --------------------------------
__device__ __forceinline__ uint32_t smem_u32(const void* p) {
    return (uint32_t)__cvta_generic_to_shared(p);
}
__device__ __forceinline__ void cp16(uint32_t dst, const void* src) {
    asm volatile("cp.async.cg.shared.global [%0], [%1], 16;" :: "r"(dst), "l"(src));
}
#define CP_COMMIT() asm volatile("cp.async.commit_group;")
#define CP_WAIT(N)  asm volatile("cp.async.wait_group %0;" :: "n"(N))

__device__ __forceinline__ void ldm_x4(uint32_t& r0, uint32_t& r1, uint32_t& r2,
                                       uint32_t& r3, uint32_t addr) {
    asm volatile("ldmatrix.sync.aligned.m8n8.x4.shared.b16 {%0,%1,%2,%3}, [%4];"
                 : "=r"(r0), "=r"(r1), "=r"(r2), "=r"(r3) : "r"(addr));
}
__device__ __forceinline__ void mma16816(float& c0, float& c1, float& c2, float& c3,
                                         uint32_t a0, uint32_t a1, uint32_t a2,
                                         uint32_t a3, uint32_t b0, uint32_t b1) {
    asm volatile(
        "mma.sync.aligned.m16n8k16.row.col.f32.f16.f16.f32 "
        "{%0,%1,%2,%3}, {%4,%5,%6,%7}, {%8,%9}, {%0,%1,%2,%3};"
        : "+f"(c0), "+f"(c1), "+f"(c2), "+f"(c3)
        : "r"(a0), "r"(a1), "r"(a2), "r"(a3), "r"(b0), "r"(b1));
}

__device__ __forceinline__ unsigned pack2h(__half a, __half b) {
    return ((unsigned)__half_as_ushort(b) << 16) | (unsigned)__half_as_ushort(a);
}

// ------------------------------ routing kernels ----------------------------
__global__ void k_init() {
    int i = blockIdx.x * 256 + threadIdx.x;
    if (i < SLOTS) g_seg_token[i] = -1;
    if (i < N_EXP) { g_counts[i] = 0; g_cursor[i] = 0; }
}

// gate + x->fp16 conversion fused (gate already streams all of x)
__global__ __launch_bounds__(256) void k_gate(const float* __restrict__ x,
                                              const float* __restrict__ gw) {
    __shared__ __align__(16) float xs[DM];
    __shared__ float lg[N_EXP];
    int t = blockIdx.x;
    const float* xr = x + (size_t)t * DM;
    uint2* xh = reinterpret_cast<uint2*>(g_xh + (size_t)t * DM);
    for (int i = threadIdx.x; i < DM / 4; i += 256) {
        float4 v = reinterpret_cast<const float4*>(xr)[i];
        reinterpret_cast<float4*>(xs)[i] = v;
        uint2 H;
        H.x = pack2h(__float2half(v.x), __float2half(v.y));
        H.y = pack2h(__float2half(v.z), __float2half(v.w));
        xh[i] = H;
    }
    __syncthreads();
    int w = threadIdx.x >> 5, lane = threadIdx.x & 31;
    const float* ge = gw + w * DM;
    float s = 0.f;
    for (int d = lane; d < DM; d += 32) s += xs[d] * ge[d];
    for (int o = 16; o; o >>= 1) s += __shfl_xor_sync(0xffffffffu, s, o);
    if (lane == 0) lg[w] = s;
    __syncthreads();
    if (threadIdx.x == 0) {
        float mx = lg[0];
        #pragma unroll
        for (int e = 1; e < N_EXP; e++) mx = fmaxf(mx, lg[e]);
        float sm[N_EXP], den = 0.f;
        #pragma unroll
        for (int e = 0; e < N_EXP; e++) { sm[e] = expf(lg[e] - mx); den += sm[e]; }
        #pragma unroll
        for (int e = 0; e < N_EXP; e++) sm[e] /= den;
        int i0 = 0;
        #pragma unroll
        for (int e = 1; e < N_EXP; e++) if (sm[e] > sm[i0]) i0 = e;
        int i1 = -1;
        #pragma unroll
        for (int e = 0; e < N_EXP; e++) {
            if (e == i0) continue;
            if (i1 < 0 || sm[e] > sm[i1]) i1 = e;
        }
        float w0 = sm[i0], w1 = sm[i1];
        float dn = w0 + w1 + 1e-20f;
        w0 /= dn; w1 /= dn;
        g_rout_e[2 * t] = i0;  g_rout_e[2 * t + 1] = i1;
        g_rout_w[2 * t] = w0;  g_rout_w[2 * t + 1] = w1;
        atomicAdd(&g_counts[i0], 1);
        atomicAdd(&g_counts[i1], 1);
    }
}

__global__ void k_scan() {
    if (threadIdx.x == 0) {
        int off = 0;
        for (int e = 0; e < N_EXP; e++) {
            g_poff[e] = off;
            off += ((g_counts[e] + 127) >> 7) << 7;   // 128-aligned segments
        }
        g_poff[N_EXP] = off;
    }
}

__global__ void k_scatter() {
    int t = blockIdx.x * 256 + threadIdx.x;
    if (t >= T_TOKENS) return;
    #pragma unroll
    for (int k = 0; k < 2; k++) {
        int e = g_rout_e[2 * t + k];
        int pos = g_poff[e] + atomicAdd(&g_cursor[e], 1);
        g_seg_token[pos] = t;
        g_seg_w[pos] = g_rout_w[2 * t + k];
    }
}

// weight f32 -> fp16 conversion (x handled in k_gate)
#define NW1Q (N_EXP * DF * DM / 4)
#define NW2Q NW1Q
#define NS1Q (DF * DM / 4)
#define NS2Q NS1Q
#define NCVTW (NW1Q + NW2Q + NS1Q + NS2Q)

__global__ __launch_bounds__(256) void k_cvt_w(const float4* __restrict__ w1,
                                               const float4* __restrict__ w2,
                                               const float4* __restrict__ ws1,
                                               const float4* __restrict__ ws2) {
    long i = (long)blockIdx.x * 256 + threadIdx.x;
    if (i >= NCVTW) return;
    long o = i;
    const float4* src;
    uint2* dst;
    if (o < NW1Q)                { src = w1;  dst = (uint2*)g_w1h; }
    else if ((o -= NW1Q) < NW2Q) { src = w2;  dst = (uint2*)g_w2h; }
    else if ((o -= NW2Q) < NS1Q) { src = ws1; dst = (uint2*)g_ws1h; }
    else { o -= NS1Q;              src = ws2; dst = (uint2*)g_ws2h; }
    float4 f = src[o];
    uint2 H;
    H.x = pack2h(__float2half(f.x), __float2half(f.y));
    H.y = pack2h(__float2half(f.z), __float2half(f.w));
    dst[o] = H;
}

// ------------------------------ HMMA GEMM ----------------------------------
// modes: 0 = fused FFN1 (y<YS shared -> g_Hsh; else routed -> g_Hh)
//        3 = shared FFN2: out = Hs@ws2 + bs2 (plain store)
//        1 = routed FFN2: atomicAdd sw*(H@w2 + b2) into out, skip pads
__device__ __forceinline__ void stage_cp(uint32_t sb, const int* __restrict__ aoff,
                                         const __half* __restrict__ Ah,
                                         const __half* __restrict__ Bh,
                                         int kb, int K, int tid) {
    #pragma unroll
    for (int i = 0; i < 4; i++) {            // A: 128 rows x 8 16B-chunks
        int j = tid + i * NTHREADS;
        int r = j >> 3, q = j & 7;
        uint32_t d = sb + r * (LDSH * 2) + q * 16;
        size_t ga = (size_t)aoff[r] + kb + q * 8;
        cp16(d, Ah + ga);
    }
    #pragma unroll
    for (int i = 0; i < 4; i++) {            // B: 128 rows x 8 16B-chunks
        int j = tid + i * NTHREADS;
        int r = j >> 3, q = j & 7;
        uint32_t d = sb + OFF_B + r * (LDSH * 2) + q * 16;
        size_t gb = (size_t)r * K + kb + q * 8;
        cp16(d, Bh + gb);
    }
}

__global__ __launch_bounds__(NTHREADS, 2) void k_gemm(int mode, int K,
                                                      const float* __restrict__ bias0,
                                                      const float* __restrict__ bias1,
                                                      float* __restrict__ outp) {
    extern __shared__ __align__(16) char dsm[];
    __shared__ int s_aoff[BM];

    int tid = threadIdx.x;
    int lane = tid & 31, w = tid >> 5;       // 8 warps
    int wm = w & 1, wn = w >> 1;             // warp grid 2(M) x 4(N), tile 64x32
    int n0 = blockIdx.x * BN;

    bool shared_path = false;                // (mode 0 only)
    int m0;
    const __half *Ah, *Bh;
    const float* bias;
    if (mode == 0) {
        shared_path = (blockIdx.y < YS);
        if (shared_path) {
            m0 = blockIdx.y * BM;            // token rows
            Ah = g_xh;
            Bh = g_ws1h + (size_t)n0 * DM;
            bias = bias1 + n0;               // bs1
        } else {
            m0 = (blockIdx.y - YS) * BM;     // slot rows
            if (m0 >= g_poff[N_EXP]) return; // pad tile
            int e = N_EXP - 1;
            #pragma unroll
            for (int q = 0; q < N_EXP; q++)
                if (m0 < g_poff[q + 1]) { e = q; break; }
            Ah = g_xh;
            Bh = g_w1h + (size_t)(e * DF + n0) * DM;
            bias = bias0 + e * DF + n0;      // b1
        }
    } else if (mode == 1) {
        m0 = blockIdx.y * BM;                // slot rows
        if (m0 >= g_poff[N_EXP]) return;
        int e = N_EXP - 1;
        #pragma unroll
        for (int q = 0; q < N_EXP; q++)
            if (m0 < g_poff[q + 1]) { e = q; break; }
        Ah = g_Hh;
        Bh = g_w2h + (size_t)(e * DM + n0) * DF;
        bias = bias0 + e * DM + n0;          // b2
    } else {                                 // mode 3
        m0 = blockIdx.y * BM;                // token rows
        Ah = g_Hsh;
        Bh = g_ws2h + (size_t)n0 * DF;
        bias = bias0 + n0;                   // bs2
    }

    if (tid < BM) {
        int r = m0 + tid;
        int off;
        if (mode == 0) {
            if (shared_path) off = r * DM;
            else { int tok = g_seg_token[r]; if (tok < 0) tok = 0; off = tok * DM; }
        } else off = r * DF;
        s_aoff[tid] = off;
    }
    __syncthreads();

    uint32_t sb0 = smem_u32(dsm);
    float acc[4][4][4];
    #pragma unroll
    for (int mt = 0; mt < 4; mt++)
        #pragma unroll
        for (int nt = 0; nt < 4; nt++)
            #pragma unroll
            for (int v = 0; v < 4; v++) acc[mt][nt][v] = 0.f;

    uint32_t a_row = wm * 64 + (lane & 15);
    uint32_t a_kof = (lane >> 4) * 8;
    uint32_t b_row = wn * 32 + (lane & 7) + ((lane >> 4) << 3);
    uint32_t b_kof = ((lane >> 3) & 1) * 8;

    const int NC = K / BK;
    stage_cp(sb0 + 0 * STG_BYTES, s_aoff, Ah, Bh, 0 * BK, K, tid);
    CP_COMMIT();
    stage_cp(sb0 + 1 * STG_BYTES, s_aoff, Ah, Bh, 1 * BK, K, tid);
    CP_COMMIT();

    int st = 0;
    for (int c = 0; c < NC; c++) {
        if (c + 1 < NC) { CP_WAIT(1); } else { CP_WAIT(0); }
        __syncthreads();
        if (c + 2 < NC) {
            int st2 = st + 2; if (st2 >= NSTAGE) st2 -= NSTAGE;
            stage_cp(sb0 + st2 * STG_BYTES, s_aoff, Ah, Bh, (c + 2) * BK, K, tid);
            CP_COMMIT();
        }

        uint32_t sbu = sb0 + st * STG_BYTES;
        #pragma unroll
        for (int ks = 0; ks < 4; ks++) {
            int kh = ks * 16;
            uint32_t bh[8];
            #pragma unroll
            for (int p = 0; p < 2; p++) {
                uint32_t ba = sbu + OFF_B +
                              ((b_row + p * 16) * LDSH + kh + b_kof) * 2;
                ldm_x4(bh[4 * p], bh[4 * p + 1], bh[4 * p + 2], bh[4 * p + 3], ba);
            }
            #pragma unroll
            for (int mt = 0; mt < 4; mt++) {
                uint32_t ah[4];
                uint32_t aa = sbu + ((a_row + mt * 16) * LDSH + kh + a_kof) * 2;
                ldm_x4(ah[0], ah[1], ah[2], ah[3], aa);
                #pragma unroll
                for (int nt = 0; nt < 4; nt++) {
                    uint32_t b0 = bh[(nt >> 1) * 4 + (nt & 1) * 2];
                    uint32_t b1 = bh[(nt >> 1) * 4 + (nt & 1) * 2 + 1];
                    float* A4 = acc[mt][nt];
                    mma16816(A4[0], A4[1], A4[2], A4[3],
                             ah[0], ah[1], ah[2], ah[3], b0, b1);
                }
            }
        }
        st++; if (st >= NSTAGE) st = 0;
    }
    __syncthreads();

    // ---------------- epilogue ----------------
    int g = lane >> 2, tig = lane & 3;
    #pragma unroll
    for (int mt = 0; mt < 4; mt++) {
        int row0 = m0 + wm * 64 + mt * 16 + g;
        int row8 = row0 + 8;
        float sw0 = 0.f, sw8 = 0.f;
        int t0 = 0, t8 = 0;
        if (mode == 1) {
            t0 = g_seg_token[row0]; t8 = g_seg_token[row8];
            sw0 = g_seg_w[row0];    sw8 = g_seg_w[row8];
        }
        #pragma unroll
        for (int nt = 0; nt < 4; nt++) {
            int colt = wn * 32 + nt * 8 + tig * 2;
            int ncol = n0 + colt;
            float b0v = bias[colt], b1v = bias[colt + 1];
            float c0 = acc[mt][nt][0], c1 = acc[mt][nt][1];
            float c2 = acc[mt][nt][2], c3 = acc[mt][nt][3];
            if (mode == 0) {
                __half* Hh = shared_path ? g_Hsh : g_Hh;
                float v00 = fmaxf(c0 + b0v, 0.f), v01 = fmaxf(c1 + b1v, 0.f);
                float v10 = fmaxf(c2 + b0v, 0.f), v11 = fmaxf(c3 + b1v, 0.f);
                *reinterpret_cast<unsigned*>(Hh + (size_t)row0 * DF + ncol) =
                    pack2h(__float2half(v00), __float2half(v01));
                *reinterpret_cast<unsigned*>(Hh + (size_t)row8 * DF + ncol) =
                    pack2h(__float2half(v10), __float2half(v11));
            } else if (mode == 3) {
                float2 o0 = make_float2(c0 + b0v, c1 + b1v);
                float2 o1 = make_float2(c2 + b0v, c3 + b1v);
                *reinterpret_cast<float2*>(outp + (size_t)row0 * DM + ncol) = o0;
                *reinterpret_cast<float2*>(outp + (size_t)row8 * DM + ncol) = o1;
            } else {
                if (t0 >= 0) {
                    atomicAdd(outp + (size_t)t0 * DM + ncol,     (c0 + b0v) * sw0);
                    atomicAdd(outp + (size_t)t0 * DM + ncol + 1, (c1 + b1v) * sw0);
                }
                if (t8 >= 0) {
                    atomicAdd(outp + (size_t)t8 * DM + ncol,     (c2 + b0v) * sw8);
                    atomicAdd(outp + (size_t)t8 * DM + ncol + 1, (c3 + b1v) * sw8);
                }
            }
        }
    }
}

// ------------------------------ host launch --------------------------------
extern "C" void kernel_launch(void* const* d_in, const int* in_sizes, int n_in,
                              void* d_out, int out_size) {
    const float* x   = (const float*)d_in[0];
    const float* gw  = (const float*)d_in[1];
    const float* w1  = (const float*)d_in[2];
    const float* b1  = (const float*)d_in[3];
    const float* w2  = (const float*)d_in[4];
    const float* b2  = (const float*)d_in[5];
    const float* ws1 = (const float*)d_in[6];
    const float* bs1 = (const float*)d_in[7];
    const float* ws2 = (const float*)d_in[8];
    const float* bs2 = (const float*)d_in[9];
    float* out = (float*)d_out;

    static bool attr_set = false;
    if (!attr_set) {
        cudaFuncSetAttribute(k_gemm, cudaFuncAttributeMaxDynamicSharedMemorySize,
                             DYN_SMEM);
        attr_set = true;
    }

    k_init<<<(SLOTS + 255) / 256, 256>>>();
    k_gate<<<T_TOKENS, 256>>>(x, gw);
    k_scan<<<1, 32>>>();
    k_scatter<<<T_TOKENS / 256, 256>>>();
    k_cvt_w<<<(NCVTW + 255) / 256, 256>>>((const float4*)w1, (const float4*)w2,
                                          (const float4*)ws1, (const float4*)ws2);
    // fused FFN1 (shared tiles y<YS, routed tiles after)
    k_gemm<<<dim3(DF / BN, YS + MTILES), NTHREADS, DYN_SMEM>>>(0, DM, b1, bs1, nullptr);
    // shared FFN2 -> writes out
    k_gemm<<<dim3(DM / BN, T_TOKENS / BM), NTHREADS, DYN_SMEM>>>(3, DF, bs2, nullptr, out);
    // routed FFN2 -> atomic accumulate into out
    k_gemm<<<dim3(DM / BN, MTILES), NTHREADS, DYN_SMEM>>>(1, DF, b2, nullptr, out);
}